// round 10
// baseline (speedup 1.0000x reference)
#include <cuda_runtime.h>
#include <cstdint>

// Pooling_38706245271888 — GB300 sm_103a
//   word_vectors        [B, T, D]  float32
//   sent_rep_token_ids  [B, S]     int32
//   sent_rep_mask       [B, S]     int32
//   sent_lengths        [B, S]     int32
//   sent_lengths_mask   [B, S]     int32
// Output: concat([rep_vec, mean_vec], axis=1) -> [B, 2S, D] float32 (+ mask tail).
#define PB 16
#define PT 4096
#define PD 768
#define PS 64
#define NTHR 192          // 192*4 == 768: thread i owns float4 at dim 4*i
#define DEPTH 8           // cp.async pipeline stages (8 x 3KB = 24KB smem)

// One CTA per (batch, sentence); R4 geometry (best so far). Main loop is a
// cp.async (LDGSTS.128) pipeline: loads go GMEM->SMEM without holding data
// registers, so DEPTH rows stay in flight per thread regardless of the
// accumulate chain. Each thread consumes ONLY its own smem bytes -> no
// __syncthreads in the loop; cp.async.wait_group gives per-thread visibility.
__global__ __launch_bounds__(NTHR, 8) void pool_kernel(
    const float* __restrict__ wv,
    const int* __restrict__ rep_ids,
    const int* __restrict__ rep_mask,
    const int* __restrict__ lengths,
    const int* __restrict__ len_mask,
    float* __restrict__ out,
    int write_mask_tail)
{
    __shared__ float4 stage[DEPTH][NTHR];
    __shared__ int s_len[PS];
    __shared__ int s_span[2];

    const int blk = blockIdx.x;          // 0 .. B*S-1
    const int b = blk / PS;
    const int j = blk % PS;
    const int tid = threadIdx.x;         // 0 .. 191
    const int d4 = tid * 4;

    // --- span via warp-parallel masked reduce (no serial 64-iter loop) ---
    if (tid < PS) s_len[tid] = lengths[b * PS + tid];
    __syncthreads();
    if (tid < 32) {
        int c = ((tid      < j) ? s_len[tid]      : 0)
              + ((tid + 32 < j) ? s_len[tid + 32] : 0);
        #pragma unroll
        for (int o = 16; o > 0; o >>= 1) c += __shfl_down_sync(0xffffffffu, c, o);
        if (tid == 0) {
            int start = c;
            int end = start + s_len[j];
            if (start > PT) start = PT;  // overflow bucket dropped
            if (end   > PT) end   = PT;
            if (end < start) end = start;
            s_span[0] = start;
            s_span[1] = end;
        }
    }
    __syncthreads();
    const int start = s_span[0];
    const int end   = s_span[1];
    const int n     = end - start;

    const float* __restrict__ base = wv + (size_t)b * PT * PD;
    const float* rowp = base + (size_t)start * PD + d4;

    float4 sum = make_float4(0.f, 0.f, 0.f, 0.f);
    float4 cnt = make_float4(0.f, 0.f, 0.f, 0.f);

    if (n >= DEPTH) {
        const uint32_t smem0 =
            (uint32_t)__cvta_generic_to_shared(&stage[0][tid]);
        const uint32_t slot_stride = NTHR * 16;

        // prime DEPTH rows, one commit group per row
        #pragma unroll
        for (int k = 0; k < DEPTH; k++) {
            uint32_t dst = smem0 + (uint32_t)k * slot_stride;
            asm volatile("cp.async.cg.shared.global [%0], [%1], 16;\n"
                         :: "r"(dst), "l"(rowp + (size_t)k * PD) : "memory");
            asm volatile("cp.async.commit_group;\n" ::: "memory");
        }

        for (int i = 0; i < n; i++) {
            // oldest row (i) complete once <= DEPTH-1 groups pending
            asm volatile("cp.async.wait_group %0;\n" :: "n"(DEPTH - 1) : "memory");
            float4 v = stage[i % DEPTH][tid];

            sum.x += v.x; sum.y += v.y; sum.z += v.z; sum.w += v.w;
            cnt.x += (v.x != 0.f) ? 1.f : 0.f;
            cnt.y += (v.y != 0.f) ? 1.f : 0.f;
            cnt.z += (v.z != 0.f) ? 1.f : 0.f;
            cnt.w += (v.w != 0.f) ? 1.f : 0.f;

            // refill freed slot; always commit to keep group count in lockstep
            int nx = i + DEPTH;
            if (nx < n) {
                uint32_t dst = smem0 + (uint32_t)(nx % DEPTH) * slot_stride;
                asm volatile("cp.async.cg.shared.global [%0], [%1], 16;\n"
                             :: "r"(dst), "l"(rowp + (size_t)nx * PD) : "memory");
            }
            asm volatile("cp.async.commit_group;\n" ::: "memory");
        }
        asm volatile("cp.async.wait_group 0;\n" ::: "memory");
    } else {
        // short-segment fallback (not hit on this dataset; correctness only)
        for (int t = 0; t < n; t++) {
            float4 v = __ldcs((const float4*)(rowp + (size_t)t * PD));
            sum.x += v.x; sum.y += v.y; sum.z += v.z; sum.w += v.w;
            cnt.x += (v.x != 0.f) ? 1.f : 0.f;
            cnt.y += (v.y != 0.f) ? 1.f : 0.f;
            cnt.z += (v.z != 0.f) ? 1.f : 0.f;
            cnt.w += (v.w != 0.f) ? 1.f : 0.f;
        }
    }

    // --- block reduce total count (empty-segment fallback detection) ---
    __shared__ float red[256];
    red[tid] = cnt.x + cnt.y + cnt.z + cnt.w;
    if (tid < 64) red[192 + tid] = 0.f;
    __syncthreads();
    for (int off = 128; off > 0; off >>= 1) {
        if (tid < off) red[tid] += red[tid + off];
        __syncthreads();
    }
    const bool empty = (red[0] == 0.f);

    const float lm = len_mask[b * PS + j] ? 1.f : 0.f;
    const float rm = rep_mask[b * PS + j] ? 1.f : 0.f;

    // --- mean vector (divide by per-dim nonzero count, min 1) ---
    float4 mv;
    if (empty) {
        mv = *(const float4*)(wv + d4);   // fallback: word_vectors[0, 0, :]
    } else {
        mv.x = sum.x / ((cnt.x == 0.f) ? 1.f : cnt.x);
        mv.y = sum.y / ((cnt.y == 0.f) ? 1.f : cnt.y);
        mv.z = sum.z / ((cnt.z == 0.f) ? 1.f : cnt.z);
        mv.w = sum.w / ((cnt.w == 0.f) ? 1.f : cnt.w);
    }
    mv.x *= lm; mv.y *= lm; mv.z *= lm; mv.w *= lm;

    // --- rep vector (gather; row recently streamed -> L2 hit) ---
    int id = rep_ids[b * PS + j];
    if (id < 0) id = 0;
    if (id >= PT) id = PT - 1;
    float4 rv = *(const float4*)(base + (size_t)id * PD + d4);
    rv.x *= rm; rv.y *= rm; rv.z *= rm; rv.w *= rm;

    // --- write: out[b, 0:S, :] = rep, out[b, S:2S, :] = mean ---
    float* orow_rep  = out + ((size_t)b * 2 * PS + j) * PD + d4;
    float* orow_mean = out + ((size_t)b * 2 * PS + PS + j) * PD + d4;
    *(float4*)orow_rep  = rv;
    *(float4*)orow_mean = mv;

    // --- mask tail (output_mask), if the harness buffer includes it ---
    if (write_mask_tail && tid == 0) {
        float* mt = out + (size_t)PB * 2 * PS * PD;
        mt[b * 2 * PS + j]      = rm;
        mt[b * 2 * PS + PS + j] = lm;
    }
}

extern "C" void kernel_launch(void* const* d_in, const int* in_sizes, int n_in,
                              void* d_out, int out_size) {
    const float* wv       = (const float*)d_in[0];
    const int*   rep_ids  = (const int*)d_in[1];
    const int*   rep_mask = (const int*)d_in[2];
    const int*   lengths  = (const int*)d_in[3];
    const int*   len_mask = (const int*)d_in[4];
    float* out = (float*)d_out;

    const int vec_elems  = PB * 2 * PS * PD;   // 1,572,864
    const int mask_elems = PB * 2 * PS;        // 2,048
    int write_mask_tail = (out_size >= vec_elems + mask_elems) ? 1 : 0;

    pool_kernel<<<PB * PS, NTHR>>>(wv, rep_ids, rep_mask, lengths, len_mask,
                                   out, write_mask_tail);
}

// round 12
// speedup vs baseline: 1.0535x; 1.0535x over previous
#include <cuda_runtime.h>
#include <cstdint>

// Pooling_38706245271888 — GB300 sm_103a
//   word_vectors        [B, T, D]  float32
//   sent_rep_token_ids  [B, S]     int32
//   sent_rep_mask       [B, S]     int32
//   sent_lengths        [B, S]     int32
//   sent_lengths_mask   [B, S]     int32
// Output: concat([rep_vec, mean_vec], axis=1) -> [B, 2S, D] float32 (+ mask tail).
#define PB 16
#define PT 4096
#define PD 768
#define PS 64
#define NTHR 192          // 192*4 == 768: thread i owns float4 at dim 4*i

// R4 geometry (best: 35.6us): one CTA per (batch, sentence), unroll-4 LDG.128
// with loads batched ahead of the FADD chain, __ldcs on the read-once stream.
// New this round: the rep-token row is CAPTURED while it streams past
// (warp-uniform predicate, ~2 issue slots/iter) instead of re-gathered from
// GMEM afterward -> removes 3MiB of DRAM re-reads. Outputs use __stcs.
__global__ __launch_bounds__(NTHR, 7) void pool_kernel(
    const float* __restrict__ wv,
    const int* __restrict__ rep_ids,
    const int* __restrict__ rep_mask,
    const int* __restrict__ lengths,
    const int* __restrict__ len_mask,
    float* __restrict__ out,
    int write_mask_tail)
{
    const int blk = blockIdx.x;          // 0 .. B*S-1
    const int b = blk / PS;
    const int j = blk % PS;
    const int tid = threadIdx.x;         // 0 .. 191
    const int d4 = tid * 4;

    // --- sentence span via warp-parallel masked reduce over lengths ---
    __shared__ int s_len[PS];
    __shared__ int s_span[2];
    if (tid < PS) s_len[tid] = lengths[b * PS + tid];
    __syncthreads();
    if (tid < 32) {
        int c = ((tid      < j) ? s_len[tid]      : 0)
              + ((tid + 32 < j) ? s_len[tid + 32] : 0);
        #pragma unroll
        for (int o = 16; o > 0; o >>= 1) c += __shfl_down_sync(0xffffffffu, c, o);
        if (tid == 0) {
            int start = c;
            int end = start + s_len[j];
            if (start > PT) start = PT;  // overflow bucket dropped
            if (end   > PT) end   = PT;
            if (end < start) end = start;
            s_span[0] = start;
            s_span[1] = end;
        }
    }
    __syncthreads();
    const int start = s_span[0];
    const int end   = s_span[1];

    // rep token id (clamped); capture its row while streaming if in-span
    int id = rep_ids[b * PS + j];
    if (id < 0) id = 0;
    if (id >= PT) id = PT - 1;

    const float* __restrict__ base = wv + (size_t)b * PT * PD;

    float4 sum = make_float4(0.f, 0.f, 0.f, 0.f);
    float4 cnt = make_float4(0.f, 0.f, 0.f, 0.f);
    float4 rv  = make_float4(0.f, 0.f, 0.f, 0.f);
    bool captured = false;

    const float* p = base + (size_t)start * PD + d4;
    int t = start;
    for (; t + 4 <= end; t += 4, p += 4 * PD) {
        float4 v0 = __ldcs((const float4*)(p));
        float4 v1 = __ldcs((const float4*)(p + PD));
        float4 v2 = __ldcs((const float4*)(p + 2 * PD));
        float4 v3 = __ldcs((const float4*)(p + 3 * PD));

        sum.x += v0.x; sum.y += v0.y; sum.z += v0.z; sum.w += v0.w;
        cnt.x += (v0.x != 0.f) ? 1.f : 0.f;
        cnt.y += (v0.y != 0.f) ? 1.f : 0.f;
        cnt.z += (v0.z != 0.f) ? 1.f : 0.f;
        cnt.w += (v0.w != 0.f) ? 1.f : 0.f;

        sum.x += v1.x; sum.y += v1.y; sum.z += v1.z; sum.w += v1.w;
        cnt.x += (v1.x != 0.f) ? 1.f : 0.f;
        cnt.y += (v1.y != 0.f) ? 1.f : 0.f;
        cnt.z += (v1.z != 0.f) ? 1.f : 0.f;
        cnt.w += (v1.w != 0.f) ? 1.f : 0.f;

        sum.x += v2.x; sum.y += v2.y; sum.z += v2.z; sum.w += v2.w;
        cnt.x += (v2.x != 0.f) ? 1.f : 0.f;
        cnt.y += (v2.y != 0.f) ? 1.f : 0.f;
        cnt.z += (v2.z != 0.f) ? 1.f : 0.f;
        cnt.w += (v2.w != 0.f) ? 1.f : 0.f;

        sum.x += v3.x; sum.y += v3.y; sum.z += v3.z; sum.w += v3.w;
        cnt.x += (v3.x != 0.f) ? 1.f : 0.f;
        cnt.y += (v3.y != 0.f) ? 1.f : 0.f;
        cnt.z += (v3.z != 0.f) ? 1.f : 0.f;
        cnt.w += (v3.w != 0.f) ? 1.f : 0.f;

        // warp-uniform capture of the rep row (taken at most once per CTA)
        if ((unsigned)(id - t) < 4u) {
            int r = id - t;
            rv = (r == 0) ? v0 : (r == 1) ? v1 : (r == 2) ? v2 : v3;
            captured = true;
        }
    }
    for (; t < end; t++, p += PD) {
        float4 v = __ldcs((const float4*)(p));
        sum.x += v.x; sum.y += v.y; sum.z += v.z; sum.w += v.w;
        cnt.x += (v.x != 0.f) ? 1.f : 0.f;
        cnt.y += (v.y != 0.f) ? 1.f : 0.f;
        cnt.z += (v.z != 0.f) ? 1.f : 0.f;
        cnt.w += (v.w != 0.f) ? 1.f : 0.f;
        if (t == id) { rv = v; captured = true; }
    }
    if (!captured) {
        // rep token outside this sentence's span (not hit on this dataset)
        rv = *(const float4*)(base + (size_t)id * PD + d4);
    }

    // --- block reduce total count (empty-segment fallback detection) ---
    __shared__ float red[256];
    red[tid] = cnt.x + cnt.y + cnt.z + cnt.w;
    if (tid < 64) red[192 + tid] = 0.f;
    __syncthreads();
    for (int off = 128; off > 0; off >>= 1) {
        if (tid < off) red[tid] += red[tid + off];
        __syncthreads();
    }
    const bool empty = (red[0] == 0.f);

    const float lm = len_mask[b * PS + j] ? 1.f : 0.f;
    const float rm = rep_mask[b * PS + j] ? 1.f : 0.f;

    // --- mean vector (divide by per-dim nonzero count, min 1) ---
    float4 mv;
    if (empty) {
        mv = *(const float4*)(wv + d4);   // fallback: word_vectors[0, 0, :]
    } else {
        mv.x = sum.x / ((cnt.x == 0.f) ? 1.f : cnt.x);
        mv.y = sum.y / ((cnt.y == 0.f) ? 1.f : cnt.y);
        mv.z = sum.z / ((cnt.z == 0.f) ? 1.f : cnt.z);
        mv.w = sum.w / ((cnt.w == 0.f) ? 1.f : cnt.w);
    }
    mv.x *= lm; mv.y *= lm; mv.z *= lm; mv.w *= lm;
    rv.x *= rm; rv.y *= rm; rv.z *= rm; rv.w *= rm;

    // --- write (streaming stores; read-never data) ---
    float* orow_rep  = out + ((size_t)b * 2 * PS + j) * PD + d4;
    float* orow_mean = out + ((size_t)b * 2 * PS + PS + j) * PD + d4;
    __stcs((float4*)orow_rep,  rv);
    __stcs((float4*)orow_mean, mv);

    // --- mask tail (output_mask), if the harness buffer includes it ---
    if (write_mask_tail && tid == 0) {
        float* mt = out + (size_t)PB * 2 * PS * PD;
        mt[b * 2 * PS + j]      = rm;
        mt[b * 2 * PS + PS + j] = lm;
    }
}

extern "C" void kernel_launch(void* const* d_in, const int* in_sizes, int n_in,
                              void* d_out, int out_size) {
    const float* wv       = (const float*)d_in[0];
    const int*   rep_ids  = (const int*)d_in[1];
    const int*   rep_mask = (const int*)d_in[2];
    const int*   lengths  = (const int*)d_in[3];
    const int*   len_mask = (const int*)d_in[4];
    float* out = (float*)d_out;

    const int vec_elems  = PB * 2 * PS * PD;   // 1,572,864
    const int mask_elems = PB * 2 * PS;        // 2,048
    int write_mask_tail = (out_size >= vec_elems + mask_elems) ? 1 : 0;

    pool_kernel<<<PB * PS, NTHR>>>(wv, rep_ids, rep_mask, lengths, len_mask,
                                   out, write_mask_tail);
}

// round 13
// speedup vs baseline: 1.1242x; 1.0671x over previous
#include <cuda_runtime.h>
#include <cstdint>

// Pooling_38706245271888 — GB300 sm_103a
//   word_vectors        [B, T, D]  float32
//   sent_rep_token_ids  [B, S]     int32
//   sent_rep_mask       [B, S]     int32
//   sent_lengths        [B, S]     int32
//   sent_lengths_mask   [B, S]     int32
// Output: concat([rep_vec, mean_vec], axis=1) -> [B, 2S, D] float32 (+ mask tail).
#define PB 16
#define PT 4096
#define PD 768
#define PS 64
#define NTHR 192          // 192*4 == 768: thread i owns float4 at dim 4*i

// R4 structure (best: 35.6us / DRAM 73.1%) with the unroll deepened 4 -> 8.
// All 8 LDG.128s issue before any FADD (MLP_p1=8); __launch_bounds__(192,7)
// raises the reg budget to 48 so the batch fits without spills (occ 7*148 =
// 1036 >= 1024 CTAs -> still a single wave). NOTHING else touches the hot
// loop: R10/R12 proved any extra in-loop work costs DRAM%.
__global__ __launch_bounds__(NTHR, 7) void pool_kernel(
    const float* __restrict__ wv,
    const int* __restrict__ rep_ids,
    const int* __restrict__ rep_mask,
    const int* __restrict__ lengths,
    const int* __restrict__ len_mask,
    float* __restrict__ out,
    int write_mask_tail)
{
    const int blk = blockIdx.x;          // 0 .. B*S-1
    const int b = blk / PS;
    const int j = blk % PS;
    const int tid = threadIdx.x;         // 0 .. 191
    const int d4 = tid * 4;

    // --- sentence span via warp-parallel masked reduce over lengths ---
    __shared__ int s_len[PS];
    __shared__ int s_span[2];
    if (tid < PS) s_len[tid] = lengths[b * PS + tid];
    __syncthreads();
    if (tid < 32) {
        int c = ((tid      < j) ? s_len[tid]      : 0)
              + ((tid + 32 < j) ? s_len[tid + 32] : 0);
        #pragma unroll
        for (int o = 16; o > 0; o >>= 1) c += __shfl_down_sync(0xffffffffu, c, o);
        if (tid == 0) {
            int start = c;
            int end = start + s_len[j];
            if (start > PT) start = PT;  // overflow bucket dropped
            if (end   > PT) end   = PT;
            if (end < start) end = start;
            s_span[0] = start;
            s_span[1] = end;
        }
    }
    __syncthreads();
    const int start = s_span[0];
    const int end   = s_span[1];

    const float* __restrict__ base = wv + (size_t)b * PT * PD;

    // --- segment sum + per-component nonzero count, unroll-8, loads first ---
    float4 sum = make_float4(0.f, 0.f, 0.f, 0.f);
    float4 cnt = make_float4(0.f, 0.f, 0.f, 0.f);

    const float* p = base + (size_t)start * PD + d4;
    int t = start;
    for (; t + 8 <= end; t += 8, p += 8 * PD) {
        float4 v0 = __ldcs((const float4*)(p));
        float4 v1 = __ldcs((const float4*)(p + PD));
        float4 v2 = __ldcs((const float4*)(p + 2 * PD));
        float4 v3 = __ldcs((const float4*)(p + 3 * PD));
        float4 v4 = __ldcs((const float4*)(p + 4 * PD));
        float4 v5 = __ldcs((const float4*)(p + 5 * PD));
        float4 v6 = __ldcs((const float4*)(p + 6 * PD));
        float4 v7 = __ldcs((const float4*)(p + 7 * PD));

        sum.x += v0.x; sum.y += v0.y; sum.z += v0.z; sum.w += v0.w;
        cnt.x += (v0.x != 0.f) ? 1.f : 0.f;
        cnt.y += (v0.y != 0.f) ? 1.f : 0.f;
        cnt.z += (v0.z != 0.f) ? 1.f : 0.f;
        cnt.w += (v0.w != 0.f) ? 1.f : 0.f;

        sum.x += v1.x; sum.y += v1.y; sum.z += v1.z; sum.w += v1.w;
        cnt.x += (v1.x != 0.f) ? 1.f : 0.f;
        cnt.y += (v1.y != 0.f) ? 1.f : 0.f;
        cnt.z += (v1.z != 0.f) ? 1.f : 0.f;
        cnt.w += (v1.w != 0.f) ? 1.f : 0.f;

        sum.x += v2.x; sum.y += v2.y; sum.z += v2.z; sum.w += v2.w;
        cnt.x += (v2.x != 0.f) ? 1.f : 0.f;
        cnt.y += (v2.y != 0.f) ? 1.f : 0.f;
        cnt.z += (v2.z != 0.f) ? 1.f : 0.f;
        cnt.w += (v2.w != 0.f) ? 1.f : 0.f;

        sum.x += v3.x; sum.y += v3.y; sum.z += v3.z; sum.w += v3.w;
        cnt.x += (v3.x != 0.f) ? 1.f : 0.f;
        cnt.y += (v3.y != 0.f) ? 1.f : 0.f;
        cnt.z += (v3.z != 0.f) ? 1.f : 0.f;
        cnt.w += (v3.w != 0.f) ? 1.f : 0.f;

        sum.x += v4.x; sum.y += v4.y; sum.z += v4.z; sum.w += v4.w;
        cnt.x += (v4.x != 0.f) ? 1.f : 0.f;
        cnt.y += (v4.y != 0.f) ? 1.f : 0.f;
        cnt.z += (v4.z != 0.f) ? 1.f : 0.f;
        cnt.w += (v4.w != 0.f) ? 1.f : 0.f;

        sum.x += v5.x; sum.y += v5.y; sum.z += v5.z; sum.w += v5.w;
        cnt.x += (v5.x != 0.f) ? 1.f : 0.f;
        cnt.y += (v5.y != 0.f) ? 1.f : 0.f;
        cnt.z += (v5.z != 0.f) ? 1.f : 0.f;
        cnt.w += (v5.w != 0.f) ? 1.f : 0.f;

        sum.x += v6.x; sum.y += v6.y; sum.z += v6.z; sum.w += v6.w;
        cnt.x += (v6.x != 0.f) ? 1.f : 0.f;
        cnt.y += (v6.y != 0.f) ? 1.f : 0.f;
        cnt.z += (v6.z != 0.f) ? 1.f : 0.f;
        cnt.w += (v6.w != 0.f) ? 1.f : 0.f;

        sum.x += v7.x; sum.y += v7.y; sum.z += v7.z; sum.w += v7.w;
        cnt.x += (v7.x != 0.f) ? 1.f : 0.f;
        cnt.y += (v7.y != 0.f) ? 1.f : 0.f;
        cnt.z += (v7.z != 0.f) ? 1.f : 0.f;
        cnt.w += (v7.w != 0.f) ? 1.f : 0.f;
    }
    for (; t < end; t++, p += PD) {
        float4 v = __ldcs((const float4*)(p));
        sum.x += v.x; sum.y += v.y; sum.z += v.z; sum.w += v.w;
        cnt.x += (v.x != 0.f) ? 1.f : 0.f;
        cnt.y += (v.y != 0.f) ? 1.f : 0.f;
        cnt.z += (v.z != 0.f) ? 1.f : 0.f;
        cnt.w += (v.w != 0.f) ? 1.f : 0.f;
    }

    // --- block reduce total count (empty-segment fallback detection) ---
    __shared__ float red[256];
    red[tid] = cnt.x + cnt.y + cnt.z + cnt.w;
    if (tid < 64) red[192 + tid] = 0.f;
    __syncthreads();
    for (int off = 128; off > 0; off >>= 1) {
        if (tid < off) red[tid] += red[tid + off];
        __syncthreads();
    }
    const bool empty = (red[0] == 0.f);

    const float lm = len_mask[b * PS + j] ? 1.f : 0.f;
    const float rm = rep_mask[b * PS + j] ? 1.f : 0.f;

    // --- mean vector (divide by per-dim nonzero count, min 1) ---
    float4 mv;
    if (empty) {
        mv = *(const float4*)(wv + d4);   // fallback: word_vectors[0, 0, :]
    } else {
        mv.x = sum.x / ((cnt.x == 0.f) ? 1.f : cnt.x);
        mv.y = sum.y / ((cnt.y == 0.f) ? 1.f : cnt.y);
        mv.z = sum.z / ((cnt.z == 0.f) ? 1.f : cnt.z);
        mv.w = sum.w / ((cnt.w == 0.f) ? 1.f : cnt.w);
    }
    mv.x *= lm; mv.y *= lm; mv.z *= lm; mv.w *= lm;

    // --- rep vector (gather; row recently streamed -> likely L2 hit) ---
    int id = rep_ids[b * PS + j];
    if (id < 0) id = 0;
    if (id >= PT) id = PT - 1;
    float4 rv = *(const float4*)(base + (size_t)id * PD + d4);
    rv.x *= rm; rv.y *= rm; rv.z *= rm; rv.w *= rm;

    // --- write: out[b, 0:S, :] = rep, out[b, S:2S, :] = mean ---
    float* orow_rep  = out + ((size_t)b * 2 * PS + j) * PD + d4;
    float* orow_mean = out + ((size_t)b * 2 * PS + PS + j) * PD + d4;
    *(float4*)orow_rep  = rv;
    *(float4*)orow_mean = mv;

    // --- mask tail (output_mask), if the harness buffer includes it ---
    if (write_mask_tail && tid == 0) {
        float* mt = out + (size_t)PB * 2 * PS * PD;
        mt[b * 2 * PS + j]      = rm;
        mt[b * 2 * PS + PS + j] = lm;
    }
}

extern "C" void kernel_launch(void* const* d_in, const int* in_sizes, int n_in,
                              void* d_out, int out_size) {
    const float* wv       = (const float*)d_in[0];
    const int*   rep_ids  = (const int*)d_in[1];
    const int*   rep_mask = (const int*)d_in[2];
    const int*   lengths  = (const int*)d_in[3];
    const int*   len_mask = (const int*)d_in[4];
    float* out = (float*)d_out;

    const int vec_elems  = PB * 2 * PS * PD;   // 1,572,864
    const int mask_elems = PB * 2 * PS;        // 2,048
    int write_mask_tail = (out_size >= vec_elems + mask_elems) ? 1 : 0;

    pool_kernel<<<PB * PS, NTHR>>>(wv, rep_ids, rep_mask, lengths, len_mask,
                                   out, write_mask_tail);
}